// round 3
// baseline (speedup 1.0000x reference)
#include <cuda_runtime.h>
#include <cuda_bf16.h>
#include <cstdint>

// TensorialCP encoder:
//   out[n, c] = lerp(vec_x[c], x_n) * lerp(vec_y[c], y_n) * lerp(vec_z[c], z_n)
// positions: [N,3] float32 in [-1,1]; vec_{x,y,z}: [32,512] float32; out: [N,32] float32.
//
// Strategy: transpose all three tables into shared memory as [513][33] floats
// (row = grid index, col = component, stride 33 for conflict-free fill+gather,
// row 512 zeroed as a safe i0+1 tap for the x==1 boundary). One warp per point,
// lane = component: 6 conflict-free 128B LDS wavefronts + one coalesced 128B STG
// per point.

#define CP_C 32
#define CP_R 512
#define CP_ROWS 513          // 512 + zero pad row for the i0+1 tap
#define CP_STRIDE 33         // 33 = 1 (mod 32): conflict-free both directions
#define AXIS_WORDS (CP_ROWS * CP_STRIDE)            // 16929
#define SMEM_BYTES (3 * AXIS_WORDS * (int)sizeof(float))  // 203148 B (< 227KB opt-in)

#define THREADS 512
#define UNROLL 8

__global__ __launch_bounds__(THREADS, 1)
void cp_encode_kernel(const float* __restrict__ pos,
                      const float* __restrict__ vx,
                      const float* __restrict__ vy,
                      const float* __restrict__ vz,
                      float* __restrict__ out,
                      int N)
{
    extern __shared__ float s[];
    float* sx = s;
    float* sy = s + AXIS_WORDS;
    float* sz = s + 2 * AXIS_WORDS;

    // ---- Fill shared tables, transposed [r][c] with stride 33 ----
    // idx = c*512 + r : consecutive threads -> consecutive r (coalesced LDG),
    // STS bank = (33r + c) % 32 = (r + c) % 32 -> conflict-free.
    for (int idx = threadIdx.x; idx < CP_C * CP_R; idx += THREADS) {
        int c = idx >> 9;          // idx / 512
        int r = idx & (CP_R - 1);  // idx % 512
        float a = vx[idx];
        float b = vy[idx];
        float d = vz[idx];
        sx[r * CP_STRIDE + c] = a;
        sy[r * CP_STRIDE + c] = b;
        sz[r * CP_STRIDE + c] = d;
    }
    // Zero pad row 512 (read only when ix lands exactly on 511; weight is 0).
    if (threadIdx.x < CP_STRIDE) {
        sx[CP_R * CP_STRIDE + threadIdx.x] = 0.0f;
        sy[CP_R * CP_STRIDE + threadIdx.x] = 0.0f;
        sz[CP_R * CP_STRIDE + threadIdx.x] = 0.0f;
    }
    __syncthreads();

    const int lane   = threadIdx.x & 31;
    const int gwarp  = (blockIdx.x * THREADS + threadIdx.x) >> 5;
    const int nwarps = (gridDim.x * THREADS) >> 5;
    const int step   = nwarps * UNROLL;

    // Per-lane base pointers (hoists the +lane*4 out of the inner loop).
    const float* __restrict__ sxl = sx + lane;
    const float* __restrict__ syl = sy + lane;
    const float* __restrict__ szl = sz + lane;

    int base;
    for (base = gwarp * UNROLL; base + UNROLL <= N; base += step) {
        const float* p = pos + (size_t)base * 3;
        float* o = out + (size_t)base * CP_C + lane;
#pragma unroll
        for (int j = 0; j < UNROLL; j++) {
            // Broadcast loads: all lanes read the same address.
            float px = __ldg(p + j * 3 + 0);
            float py = __ldg(p + j * 3 + 1);
            float pz = __ldg(p + j * 3 + 2);

            // ix = (x + 1) * 0.5 * (R - 1), single-rounded; exact-0 at x = -1,
            // and x in [-1,1] keeps i0 in [0,511] (511 only when w == 0).
            float ixf = fmaf(px, 255.5f, 255.5f);
            float iyf = fmaf(py, 255.5f, 255.5f);
            float izf = fmaf(pz, 255.5f, 255.5f);
            float fx0 = floorf(ixf);
            float fy0 = floorf(iyf);
            float fz0 = floorf(izf);
            float wx = ixf - fx0;
            float wy = iyf - fy0;
            float wz = izf - fz0;
            int ix = (int)fx0;
            int iy = (int)fy0;
            int iz = (int)fz0;

            // Conflict-free gathers; second tap via immediate offset (+STRIDE).
            float gx0 = sxl[ix * CP_STRIDE];
            float gx1 = sxl[ix * CP_STRIDE + CP_STRIDE];
            float gy0 = syl[iy * CP_STRIDE];
            float gy1 = syl[iy * CP_STRIDE + CP_STRIDE];
            float gz0 = szl[iz * CP_STRIDE];
            float gz1 = szl[iz * CP_STRIDE + CP_STRIDE];

            float fx = fmaf(wx, gx1 - gx0, gx0);
            float fy = fmaf(wy, gy1 - gy0, gy0);
            float fz = fmaf(wz, gz1 - gz0, gz0);

            o[j * CP_C] = fx * fy * fz;   // coalesced 128B per warp per point
        }
    }
    // Tail (at most UNROLL-1 points for a few warps).
    for (int n = base; n < N; n++) {
        float px = __ldg(pos + (size_t)n * 3 + 0);
        float py = __ldg(pos + (size_t)n * 3 + 1);
        float pz = __ldg(pos + (size_t)n * 3 + 2);
        float ixf = fmaf(px, 255.5f, 255.5f);
        float iyf = fmaf(py, 255.5f, 255.5f);
        float izf = fmaf(pz, 255.5f, 255.5f);
        float fx0 = floorf(ixf), fy0 = floorf(iyf), fz0 = floorf(izf);
        float wx = ixf - fx0, wy = iyf - fy0, wz = izf - fz0;
        int ix = (int)fx0, iy = (int)fy0, iz = (int)fz0;
        float gx0 = sxl[ix * CP_STRIDE], gx1 = sxl[ix * CP_STRIDE + CP_STRIDE];
        float gy0 = syl[iy * CP_STRIDE], gy1 = syl[iy * CP_STRIDE + CP_STRIDE];
        float gz0 = szl[iz * CP_STRIDE], gz1 = szl[iz * CP_STRIDE + CP_STRIDE];
        float fx = fmaf(wx, gx1 - gx0, gx0);
        float fy = fmaf(wy, gy1 - gy0, gy0);
        float fz = fmaf(wz, gz1 - gz0, gz0);
        out[(size_t)n * CP_C + lane] = fx * fy * fz;
    }
}

extern "C" void kernel_launch(void* const* d_in, const int* in_sizes, int n_in,
                              void* d_out, int out_size)
{
    const float* pos = (const float*)d_in[0];
    const float* vx  = (const float*)d_in[1];
    const float* vy  = (const float*)d_in[2];
    const float* vz  = (const float*)d_in[3];
    float* out = (float*)d_out;

    int N = in_sizes[0] / 3;

    int sms = 148;
    cudaDeviceGetAttribute(&sms, cudaDevAttrMultiProcessorCount, 0);

    cudaFuncSetAttribute(cp_encode_kernel,
                         cudaFuncAttributeMaxDynamicSharedMemorySize, SMEM_BYTES);

    cp_encode_kernel<<<sms, THREADS, SMEM_BYTES>>>(pos, vx, vy, vz, out, N);
}